// round 1
// baseline (speedup 1.0000x reference)
#include <cuda_runtime.h>
#include <math.h>
#include <stdint.h>

#define T      4096
#define H      1024
#define IDIM   512
#define E      64
#define TOPK   2
#define TM     16
#define PPOS   (T*TOPK + E*TM)          // 9216 padded positions
#define MAXTILES (T*TOPK/TM + E)        // 576 worst-case tiles

// -------- scratch (device globals; no allocation allowed) --------
__device__ int   g_counts[E];
__device__ int   g_off[E+1];
__device__ int   g_tile_off[E+1];
__device__ int   g_cursor[E];
__device__ int   g_perm[PPOS];
__device__ float g_pw[PPOS];
__device__ int   g_sel[T*TOPK];
__device__ float g_w[T*TOPK];

// ---------------- init: zero out, counts, perm ----------------
__global__ void k_init(float* __restrict__ out) {
    int idx = blockIdx.x * blockDim.x + threadIdx.x;
    int stride = gridDim.x * blockDim.x;
    for (int i = idx; i < T * H; i += stride) out[i] = 0.f;
    if (idx < E) g_counts[idx] = 0;
    for (int i = idx; i < PPOS; i += stride) g_perm[i] = -1;
}

// ---------------- router: logits -> top2 -> weights ----------------
__global__ void __launch_bounds__(256) k_router(const float* __restrict__ x,
                                                const float* __restrict__ gw,
                                                const float* __restrict__ gb) {
    __shared__ float xs[H];
    __shared__ float red[256];
    __shared__ float logits[E];
    const int t = blockIdx.x;
    const int tid = threadIdx.x;

    const float4* xp4 = (const float4*)(x + (size_t)t * H);
    float4* xs4 = (float4*)xs;
    for (int i = tid; i < H / 4; i += 256) xs4[i] = xp4[i];
    __syncthreads();

    // 256 threads = 64 experts x 4 chunks of 256 H-elements
    const int e = tid & 63;
    const int chunk = tid >> 6;
    const float4* gwp = (const float4*)(gw + (size_t)e * H + chunk * 256);
    const float4* xc = (const float4*)(xs + chunk * 256);
    float acc = 0.f;
#pragma unroll 4
    for (int j = 0; j < 64; j++) {
        float4 wv = gwp[j];
        float4 xv = xc[j];
        acc += xv.x * wv.x + xv.y * wv.y + xv.z * wv.z + xv.w * wv.w;
    }
    red[tid] = acc;
    __syncthreads();
    if (tid < E)
        logits[tid] = red[tid] + red[tid + 64] + red[tid + 128] + red[tid + 192] + gb[tid];
    __syncthreads();

    if (tid == 0) {
        float l0 = -1e30f, l1 = -1e30f;
        int e0 = 0, e1 = 0;
        for (int k = 0; k < E; k++) {
            float l = logits[k];
            if (l > l0)      { l1 = l0; e1 = e0; l0 = l; e0 = k; }
            else if (l > l1) { l1 = l;  e1 = k; }
        }
        // renormalized top-2 softmax weights == 2-way softmax over (l0,l1)
        float r  = expf(l1 - l0);
        float w0 = 1.f / (1.f + r);
        float w1 = r * w0;
        g_sel[2 * t] = e0;  g_sel[2 * t + 1] = e1;
        g_w[2 * t]   = w0;  g_w[2 * t + 1]   = w1;
        atomicAdd(&g_counts[e0], 1);
        atomicAdd(&g_counts[e1], 1);
    }
}

// ---------------- scan: padded offsets + tile offsets ----------------
__global__ void k_scan() {
    if (blockIdx.x == 0 && threadIdx.x == 0) {
        int off = 0, toff = 0;
        for (int e = 0; e < E; e++) {
            g_off[e] = off;
            g_tile_off[e] = toff;
            g_cursor[e] = off;
            int tiles = (g_counts[e] + TM - 1) / TM;
            off += tiles * TM;
            toff += tiles;
        }
        g_off[E] = off;
        g_tile_off[E] = toff;
    }
}

// ---------------- scatter: fill per-expert token lists ----------------
__global__ void k_scatter() {
    int idx = blockIdx.x * blockDim.x + threadIdx.x;
    if (idx >= T * TOPK) return;
    int e = g_sel[idx];
    int pos = atomicAdd(&g_cursor[e], 1);
    g_perm[pos] = idx >> 1;
    g_pw[pos] = g_w[idx];
}

// ---------------- grouped expert FFN ----------------
// one block = one expert x 16-token tile. smem: xs[16][1024] + as[16][512]
__global__ void __launch_bounds__(256, 2) k_ffn(const float* __restrict__ x,
                                                const float* __restrict__ W1,
                                                const float* __restrict__ W2,
                                                const float* __restrict__ W3,
                                                float* __restrict__ out) {
    const int tile = blockIdx.x;
    if (tile >= g_tile_off[E]) return;

    // binary search for expert owning this tile
    int lo = 0, hi = E;
    while (lo + 1 < hi) {
        int mid = (lo + hi) >> 1;
        if (g_tile_off[mid] <= tile) lo = mid; else hi = mid;
    }
    const int e = lo;
    const int p0 = g_off[e] + (tile - g_tile_off[e]) * TM;

    __shared__ int   s_tok[TM];
    __shared__ float s_w[TM];
    extern __shared__ float smem[];
    float* xs = smem;               // TM * H floats
    float* as = smem + TM * H;      // TM * IDIM floats
    float4* xs4 = (float4*)xs;
    float4* as4 = (float4*)as;

    const int tid = threadIdx.x;
    if (tid < TM) {
        int tok = g_perm[p0 + tid];
        s_tok[tid] = tok;
        s_w[tid] = (tok >= 0) ? g_pw[p0 + tid] : 0.f;
    }
    __syncthreads();

    // load x tile (zeros for padded rows)
    for (int idx4 = tid; idx4 < TM * (H / 4); idx4 += 256) {
        int r = idx4 / (H / 4);
        int h4 = idx4 % (H / 4);
        int tok = s_tok[r];
        float4 v = make_float4(0.f, 0.f, 0.f, 0.f);
        if (tok >= 0) v = ((const float4*)(x + (size_t)tok * H))[h4];
        xs4[idx4] = v;
    }
    __syncthreads();

    // phase 1: h1 = x W1^T, h3 = x W3^T, a = silu(h1)*h3*w
    for (int pass = 0; pass < 2; pass++) {
        const int i = tid + pass * 256;
        const float4* w1p = (const float4*)(W1 + ((size_t)e * IDIM + i) * H);
        const float4* w3p = (const float4*)(W3 + ((size_t)e * IDIM + i) * H);
        float acc1[TM], acc3[TM];
#pragma unroll
        for (int r = 0; r < TM; r++) { acc1[r] = 0.f; acc3[r] = 0.f; }
        for (int h4 = 0; h4 < H / 4; h4++) {
            float4 w1v = w1p[h4];
            float4 w3v = w3p[h4];
#pragma unroll
            for (int r = 0; r < TM; r++) {
                float4 xv = xs4[r * (H / 4) + h4];
                acc1[r] += xv.x * w1v.x + xv.y * w1v.y + xv.z * w1v.z + xv.w * w1v.w;
                acc3[r] += xv.x * w3v.x + xv.y * w3v.y + xv.z * w3v.z + xv.w * w3v.w;
            }
        }
#pragma unroll
        for (int r = 0; r < TM; r++) {
            float h1 = acc1[r];
            float sig = 1.f / (1.f + expf(-h1));
            as[r * IDIM + i] = h1 * sig * acc3[r] * s_w[r];
        }
    }
    __syncthreads();

    // phase 2: y = a W2^T, scatter-add into out
    for (int pass = 0; pass < 4; pass++) {
        const int h = tid + pass * 256;
        const float4* w2p = (const float4*)(W2 + ((size_t)e * H + h) * IDIM);
        float acc[TM];
#pragma unroll
        for (int r = 0; r < TM; r++) acc[r] = 0.f;
        for (int i4 = 0; i4 < IDIM / 4; i4++) {
            float4 wv = w2p[i4];
#pragma unroll
            for (int r = 0; r < TM; r++) {
                float4 av = as4[r * (IDIM / 4) + i4];
                acc[r] += av.x * wv.x + av.y * wv.y + av.z * wv.z + av.w * wv.w;
            }
        }
#pragma unroll
        for (int r = 0; r < TM; r++) {
            int tok = s_tok[r];
            if (tok >= 0) atomicAdd(out + (size_t)tok * H + h, acc[r]);
        }
    }
}

// ---------------- launch ----------------
extern "C" void kernel_launch(void* const* d_in, const int* in_sizes, int n_in,
                              void* d_out, int out_size) {
    const float* x  = (const float*)d_in[0];
    const float* gw = (const float*)d_in[1];
    const float* gb = (const float*)d_in[2];
    const float* W1 = (const float*)d_in[3];
    const float* W2 = (const float*)d_in[4];
    const float* W3 = (const float*)d_in[5];
    float* out = (float*)d_out;

    const int ffn_smem = (TM * H + TM * IDIM) * (int)sizeof(float);  // 96 KB
    cudaFuncSetAttribute(k_ffn, cudaFuncAttributeMaxDynamicSharedMemorySize, ffn_smem);

    k_init<<<512, 256>>>(out);
    k_router<<<T, 256>>>(x, gw, gb);
    k_scan<<<1, 32>>>();
    k_scatter<<<(T * TOPK + 255) / 256, 256>>>();
    k_ffn<<<MAXTILES, 256, ffn_smem>>>(x, W1, W2, W3, out);
}